// round 7
// baseline (speedup 1.0000x reference)
#include <cuda_runtime.h>
#include <float.h>

// Problem constants: x [16, 256, 32, 32] -> [N=16, C=256, L=1024]
#define NB 16
#define CC 256
#define LLEN 1024

// ---------------- scratch (__device__ globals; no allocations allowed) -----
__device__ float g_wcat[2 * CC * CC];          // [512, 256]: Mk=Wt^T@Wp / Weff=Wr@Wg
__device__ float g_qg[NB * 2 * CC * LLEN];     // [n][512][1024]  q, geff
__device__ float g_tmax[NB * 64];              // per-tile max of c
__device__ float g_tsum[NB * 64];              // per-tile sum exp(c - tile max)
__device__ float g_mxz[NB];                    // max + ln(sum exp(c - max)) per n

typedef unsigned long long ull;

__device__ __forceinline__ ull pack2(float x, float y) {
    ull r; asm("mov.b64 %0,{%1,%2};" : "=l"(r) : "f"(x), "f"(y)); return r;
}
__device__ __forceinline__ void unpack2(ull v, float& x, float& y) {
    asm("mov.b64 {%0,%1},%2;" : "=f"(x), "=f"(y) : "l"(v));
}
// Packed f32x2 FMA (sm_100+): 2x fp32 FMA throughput vs scalar FFMA.
__device__ __forceinline__ ull ffma2(ull a, ull b, ull c) {
    ull d; asm("fma.rn.f32x2 %0,%1,%2,%3;" : "=l"(d) : "l"(a), "l"(b), "l"(c)); return d;
}

// ---------------------------------------------------------------------------
// Generic batched SGEMM: C[n] = op(A[n]) * op(B[n]) (+ X[n])
//   Tile: BM=BN=128, BK=16, 256 threads, 8x8 per thread, f32x2 inner loop.
//   Register prefetch + double-buffered smem: one __syncthreads per k-tile.
//   AT=false: A row-major [M x K]; AT=true: A K-major [K x M] (computes A^T B).
//   B always [K x N] row-major.
//   EXPB: B element e = exp(b - mxz[n])      (softmax fused into B load)
//   ADDX: epilogue adds X (residual)
//   STATS: epilogue emits per-tile (max, sum exp) of C for global softmax
//   All dims divide tiles exactly.
// ---------------------------------------------------------------------------
template <bool AT, bool EXPB, bool ADDX, bool STATS>
__global__ __launch_bounds__(256, 2) void gemm128(
    const float* __restrict__ A, const float* __restrict__ B,
    float* __restrict__ C, const float* __restrict__ X,
    int K, int lda, int ldb, int ldc,
    long sA, long sB, long sC)
{
    const int bz = blockIdx.z;
    A += (long)bz * sA;
    B += (long)bz * sB;
    C += (long)bz * sC;
    if (ADDX) X += (long)bz * sC;

    const int m0 = blockIdx.y * 128;
    const int n0 = blockIdx.x * 128;
    const int tid = threadIdx.x;
    const int tr = tid >> 4;   // 0..15 -> 8 rows each
    const int tc = tid & 15;   // 0..15 -> 8 cols each

    __shared__ float As[2][16][128];
    __shared__ float Bs[2][16][128];

    float mxz = 0.f;
    if (EXPB) mxz = g_mxz[bz];

    ull acc[8][4];
#pragma unroll
    for (int i = 0; i < 8; i++)
#pragma unroll
        for (int j = 0; j < 4; j++) acc[i][j] = 0ull;

    // per-thread source coordinates (constant across k-tiles)
    const int a_k  = tid >> 5;          // AT: k row within tile (0..7), +t*8
    const int a_m4 = (tid & 31) * 4;    // AT: m offset
    const int a_m  = tid >> 2;          // !AT: m row within tile (0..63), +t*64
    const int a_kc = (tid & 3) * 4;     // !AT: k offset
    const int b_k  = tid >> 5;
    const int b_n4 = (tid & 31) * 4;

    float4 ra[2], rb[2];

    auto load_tile = [&](int kk) {
        if (AT) {
#pragma unroll
            for (int t = 0; t < 2; t++)
                ra[t] = *(const float4*)(A + (long)(kk + a_k + t * 8) * lda + m0 + a_m4);
        } else {
#pragma unroll
            for (int t = 0; t < 2; t++)
                ra[t] = *(const float4*)(A + (long)(m0 + a_m + t * 64) * lda + kk + a_kc);
        }
#pragma unroll
        for (int t = 0; t < 2; t++)
            rb[t] = *(const float4*)(B + (long)(kk + b_k + t * 8) * ldb + n0 + b_n4);
    };
    auto store_tile = [&](int buf) {
        if (AT) {
#pragma unroll
            for (int t = 0; t < 2; t++)
                *(float4*)&As[buf][a_k + t * 8][a_m4] = ra[t];
        } else {
#pragma unroll
            for (int t = 0; t < 2; t++) {
                const int m = a_m + t * 64;
                As[buf][a_kc + 0][m] = ra[t].x; As[buf][a_kc + 1][m] = ra[t].y;
                As[buf][a_kc + 2][m] = ra[t].z; As[buf][a_kc + 3][m] = ra[t].w;
            }
        }
#pragma unroll
        for (int t = 0; t < 2; t++) {
            float4 v = rb[t];
            if (EXPB) {
                v.x = __expf(v.x - mxz);
                v.y = __expf(v.y - mxz);
                v.z = __expf(v.z - mxz);
                v.w = __expf(v.w - mxz);
            }
            *(float4*)&Bs[buf][b_k + t * 8][b_n4] = v;
        }
    };

    // prologue: tile 0 into buffer 0
    load_tile(0);
    store_tile(0);

    int cur = 0;
    for (int k0 = 0; k0 < K; k0 += 16) {
        __syncthreads();                     // buf[cur] fully written / prev reads done

        const int k1 = k0 + 16;
        if (k1 < K) load_tile(k1);           // LDGs overlap the FMA slab below

#pragma unroll
        for (int k = 0; k < 16; k++) {
            const float4 b0 = *(const float4*)&Bs[cur][k][tc * 8];
            const float4 b1 = *(const float4*)&Bs[cur][k][tc * 8 + 4];
            const float4 a0 = *(const float4*)&As[cur][k][tr * 8];
            const float4 a1 = *(const float4*)&As[cur][k][tr * 8 + 4];
            ull b2[4];
            b2[0] = pack2(b0.x, b0.y); b2[1] = pack2(b0.z, b0.w);
            b2[2] = pack2(b1.x, b1.y); b2[3] = pack2(b1.z, b1.w);
            const float av[8] = {a0.x, a0.y, a0.z, a0.w, a1.x, a1.y, a1.z, a1.w};
#pragma unroll
            for (int i = 0; i < 8; i++) {
                const ull a2 = pack2(av[i], av[i]);
#pragma unroll
                for (int j = 0; j < 4; j++) acc[i][j] = ffma2(a2, b2[j], acc[i][j]);
            }
        }

        if (k1 < K) store_tile(cur ^ 1);     // opposite buffer; ordered by next sync
        cur ^= 1;
    }

    float lmax = -FLT_MAX;

#pragma unroll
    for (int i = 0; i < 8; i++) {
        float o[8];
#pragma unroll
        for (int j = 0; j < 4; j++) unpack2(acc[i][j], o[2 * j], o[2 * j + 1]);
        const long off = (long)(m0 + tr * 8 + i) * ldc + n0 + tc * 8;
        if (ADDX) {
            const float4 x0 = *(const float4*)(X + off);
            const float4 x1 = *(const float4*)(X + off + 4);
            o[0] += x0.x; o[1] += x0.y; o[2] += x0.z; o[3] += x0.w;
            o[4] += x1.x; o[5] += x1.y; o[6] += x1.z; o[7] += x1.w;
        }
        if (STATS) {
#pragma unroll
            for (int j = 0; j < 8; j++) lmax = fmaxf(lmax, o[j]);
        }
        *(float4*)(C + off)     = make_float4(o[0], o[1], o[2], o[3]);
        *(float4*)(C + off + 4) = make_float4(o[4], o[5], o[6], o[7]);
    }

    if (STATS) {
        // second pass over the (still-live) accumulators: sum exp(v - lmax)
        float lsum = 0.f;
#pragma unroll
        for (int i = 0; i < 8; i++)
#pragma unroll
            for (int j = 0; j < 4; j++) {
                float v0, v1; unpack2(acc[i][j], v0, v1);
                lsum += __expf(v0 - lmax) + __expf(v1 - lmax);
            }
        // warp-level online-softmax merge
#pragma unroll
        for (int s = 16; s; s >>= 1) {
            const float om = __shfl_xor_sync(0xffffffffu, lmax, s);
            const float os = __shfl_xor_sync(0xffffffffu, lsum, s);
            const float nm = fmaxf(lmax, om);
            lsum = lsum * __expf(lmax - nm) + os * __expf(om - nm);
            lmax = nm;
        }
        __shared__ float smx[8], sms[8];
        if ((tid & 31) == 0) { smx[tid >> 5] = lmax; sms[tid >> 5] = lsum; }
        __syncthreads();
        if (tid == 0) {
            float M = smx[0], S = sms[0];
#pragma unroll
            for (int w = 1; w < 8; w++) {
                const float nm = fmaxf(M, smx[w]);
                S = S * __expf(M - nm) + sms[w] * __expf(smx[w] - nm);
                M = nm;
            }
            const int tile = bz * 64 + blockIdx.y * 8 + blockIdx.x;
            g_tmax[tile] = M;
            g_tsum[tile] = S;
        }
    }
}

// ---- fold 64 per-tile (max, sumexp) pairs per sample into mxz = max+lnZ ----
__global__ void combine_stats_k() {           // grid NB, 32 threads
    const int n = blockIdx.x;
    const int t = threadIdx.x;
    float m0 = g_tmax[n * 64 + t],      s0 = g_tsum[n * 64 + t];
    float m1 = g_tmax[n * 64 + 32 + t], s1 = g_tsum[n * 64 + 32 + t];
    float M = fmaxf(m0, m1);
    float S = s0 * __expf(m0 - M) + s1 * __expf(m1 - M);
#pragma unroll
    for (int s = 16; s; s >>= 1) {
        const float om = __shfl_xor_sync(0xffffffffu, M, s);
        const float os = __shfl_xor_sync(0xffffffffu, S, s);
        const float nm = fmaxf(M, om);
        S = S * __expf(M - nm) + os * __expf(om - nm);
        M = nm;
    }
    if (t == 0) g_mxz[n] = M + logf(S);
}

// ---------------------------------------------------------------------------
extern "C" void kernel_launch(void* const* d_in, const int* in_sizes, int n_in,
                              void* d_out, int out_size)
{
    const float* x  = (const float*)d_in[0];
    const float* wt = (const float*)d_in[1];
    const float* wp = (const float*)d_in[2];
    const float* wg = (const float*)d_in[3];
    const float* wr = (const float*)d_in[4];

    float* outc = (float*)d_out;                       // c: [16, 1024, 1024]
    float* out2 = outc + (long)NB * LLEN * LLEN;       // x + attn: [16, 256, 32, 32]

    float *wcat, *qg;
    cudaGetSymbolAddress((void**)&wcat, g_wcat);
    cudaGetSymbolAddress((void**)&qg,   g_qg);

    const long sX  = (long)CC * LLEN;         // 262144: per-n stride of x / out2
    const long sQG = (long)2 * CC * LLEN;     // 524288
    const long sCC = (long)LLEN * LLEN;       // 1048576: per-n stride of c

    // Wcat rows 0..255:  Mk   = Wt^T @ Wp   [256 x 256 x 256]
    gemm128<true, false, false, false><<<dim3(2, 2, 1), 256>>>(
        wt, wp, wcat, nullptr, 256, 256, 256, 256, 0, 0, 0);

    // Wcat rows 256..511: Weff = Wr @ Wg    [256 x 256 x 256]
    gemm128<false, false, false, false><<<dim3(2, 2, 1), 256>>>(
        wr, wg, wcat + CC * CC, nullptr, 256, 256, 256, 256, 0, 0, 0);

    // q, geff = Wcat @ x[n]        [512 x 1024 x 256]
    gemm128<false, false, false, false><<<dim3(8, 4, NB), 256>>>(
        wcat, x, qg, nullptr, 256, 256, 1024, 1024, 0, sX, sQG);

    // c = x^T @ q  (+ per-tile softmax stats from registers)  -> d_out
    gemm128<true, false, false, true><<<dim3(8, 8, NB), 256>>>(
        x, qg, outc, nullptr, 256, 1024, 1024, 1024, sX, sQG, sCC);

    // fold 64 tile-stats per sample into g_mxz
    combine_stats_k<<<NB, 32>>>();

    // out = x + geff @ softmax(c)  [256 x 1024 x 1024]:
    // exp(b - mxz) fused into B load, residual fused into epilogue
    gemm128<false, true, true, false><<<dim3(8, 2, NB), 256>>>(
        qg + CC * LLEN, outc, out2, x, 1024, 1024, 1024, 1024, sQG, sCC, sX);
}

// round 12
// speedup vs baseline: 1.2065x; 1.2065x over previous
#include <cuda_runtime.h>
#include <float.h>

// Problem constants: x [16, 256, 32, 32] -> [N=16, C=256, L=1024]
#define NB 16
#define CC 256
#define LLEN 1024

// ---------------- scratch (__device__ globals; no allocations allowed) -----
__device__ float g_wcat[2 * CC * CC];          // [512, 256]: Mk=Wt^T@Wp / Weff=Wr@Wg
__device__ float g_qg[NB * 2 * CC * LLEN];     // [n][512][1024]  q, geff
__device__ float g_tmax[NB * 64];              // per-tile max of c
__device__ float g_tsum[NB * 64];              // per-tile sum exp(c - tile max)

typedef unsigned long long ull;

__device__ __forceinline__ ull pack2(float x, float y) {
    ull r; asm("mov.b64 %0,{%1,%2};" : "=l"(r) : "f"(x), "f"(y)); return r;
}
__device__ __forceinline__ void unpack2(ull v, float& x, float& y) {
    asm("mov.b64 {%0,%1},%2;" : "=f"(x), "=f"(y) : "l"(v));
}
// Packed f32x2 FMA (sm_100+): 2x fp32 FMA throughput vs scalar FFMA.
__device__ __forceinline__ ull ffma2(ull a, ull b, ull c) {
    ull d; asm("fma.rn.f32x2 %0,%1,%2,%3;" : "=l"(d) : "l"(a), "l"(b), "l"(c)); return d;
}

// ---------------------------------------------------------------------------
// Generic batched SGEMM: C[n] = op(A[n]) * op(B[n]) (+ X[n])
//   Tile: BM=BN=128, BK=16, 256 threads, 8x8 per thread, f32x2 inner loop.
//   Register prefetch + double-buffered smem: one __syncthreads per k-tile.
//   B fragment = cols {tc*4..+3} u {64+tc*4..+3}: lane-contiguous LDS
//   (conflict-free; the old tc*8 mapping was 2-way conflicted every read).
//   As rows padded to 132 floats: !AT transpose-scatter 4-way -> 2-way.
//   AT=false: A row-major [M x K]; AT=true: A K-major [K x M] (computes A^T B).
//   B always [K x N] row-major.
//   EXPB: B element e = exp(b - mxz[n]), mxz folded from tile stats in-kernel
//   ADDX: epilogue adds X (residual)
//   STATS: epilogue emits per-tile (max, sum exp) of C for global softmax
// ---------------------------------------------------------------------------
template <bool AT, bool EXPB, bool ADDX, bool STATS>
__global__ __launch_bounds__(256, 2) void gemm128(
    const float* __restrict__ A, const float* __restrict__ B,
    float* __restrict__ C, const float* __restrict__ X,
    int K, int lda, int ldb, int ldc,
    long sA, long sB, long sC)
{
    const int bz = blockIdx.z;
    A += (long)bz * sA;
    B += (long)bz * sB;
    C += (long)bz * sC;
    if (ADDX) X += (long)bz * sC;

    const int m0 = blockIdx.y * 128;
    const int n0 = blockIdx.x * 128;
    const int tid = threadIdx.x;
    const int tr = tid >> 4;   // 0..15 -> 8 rows each
    const int tc = tid & 15;   // 0..15 -> 4+4 cols each

    __shared__ float As[2][16][132];
    __shared__ float Bs[2][16][128];
    __shared__ float s_mxz;

    float mxz = 0.f;
    if (EXPB) {
        // fold the 64 per-tile (max, sumexp) pairs of sample bz -> mxz
        if (tid < 32) {
            const float m0_ = g_tmax[bz * 64 + tid],      s0_ = g_tsum[bz * 64 + tid];
            const float m1_ = g_tmax[bz * 64 + 32 + tid], s1_ = g_tsum[bz * 64 + 32 + tid];
            float M = fmaxf(m0_, m1_);
            float S = s0_ * __expf(m0_ - M) + s1_ * __expf(m1_ - M);
#pragma unroll
            for (int s = 16; s; s >>= 1) {
                const float om = __shfl_xor_sync(0xffffffffu, M, s);
                const float os = __shfl_xor_sync(0xffffffffu, S, s);
                const float nm = fmaxf(M, om);
                S = S * __expf(M - nm) + os * __expf(om - nm);
                M = nm;
            }
            if (tid == 0) s_mxz = M + logf(S);
        }
        __syncthreads();
        mxz = s_mxz;
    }

    ull acc[8][4];
#pragma unroll
    for (int i = 0; i < 8; i++)
#pragma unroll
        for (int j = 0; j < 4; j++) acc[i][j] = 0ull;

    // per-thread source coordinates (constant across k-tiles)
    const int a_k  = tid >> 5;          // AT: k row within tile (0..7), +t*8
    const int a_m4 = (tid & 31) * 4;    // AT: m offset
    const int a_m  = tid >> 2;          // !AT: m row within tile (0..63), +t*64
    const int a_kc = (tid & 3) * 4;     // !AT: k offset
    const int b_k  = tid >> 5;
    const int b_n4 = (tid & 31) * 4;

    float4 ra[2], rb[2];

    auto load_tile = [&](int kk) {
        if (AT) {
#pragma unroll
            for (int t = 0; t < 2; t++)
                ra[t] = *(const float4*)(A + (long)(kk + a_k + t * 8) * lda + m0 + a_m4);
        } else {
#pragma unroll
            for (int t = 0; t < 2; t++)
                ra[t] = *(const float4*)(A + (long)(m0 + a_m + t * 64) * lda + kk + a_kc);
        }
#pragma unroll
        for (int t = 0; t < 2; t++)
            rb[t] = *(const float4*)(B + (long)(kk + b_k + t * 8) * ldb + n0 + b_n4);
    };
    auto store_tile = [&](int buf) {
        if (AT) {
#pragma unroll
            for (int t = 0; t < 2; t++)
                *(float4*)&As[buf][a_k + t * 8][a_m4] = ra[t];
        } else {
#pragma unroll
            for (int t = 0; t < 2; t++) {
                const int m = a_m + t * 64;
                As[buf][a_kc + 0][m] = ra[t].x; As[buf][a_kc + 1][m] = ra[t].y;
                As[buf][a_kc + 2][m] = ra[t].z; As[buf][a_kc + 3][m] = ra[t].w;
            }
        }
#pragma unroll
        for (int t = 0; t < 2; t++) {
            float4 v = rb[t];
            if (EXPB) {
                v.x = __expf(v.x - mxz);
                v.y = __expf(v.y - mxz);
                v.z = __expf(v.z - mxz);
                v.w = __expf(v.w - mxz);
            }
            *(float4*)&Bs[buf][b_k + t * 8][b_n4] = v;
        }
    };

    // prologue: tile 0 into buffer 0
    load_tile(0);
    store_tile(0);

    int cur = 0;
    for (int k0 = 0; k0 < K; k0 += 16) {
        __syncthreads();                     // buf[cur] fully written / prev reads done

        const int k1 = k0 + 16;
        if (k1 < K) load_tile(k1);           // LDGs overlap the FMA slab below

#pragma unroll
        for (int k = 0; k < 16; k++) {
            const float4 b0 = *(const float4*)&Bs[cur][k][tc * 4];        // conflict-free
            const float4 b1 = *(const float4*)&Bs[cur][k][64 + tc * 4];   // conflict-free
            const float4 a0 = *(const float4*)&As[cur][k][tr * 8];        // broadcast
            const float4 a1 = *(const float4*)&As[cur][k][tr * 8 + 4];
            ull b2[4];
            b2[0] = pack2(b0.x, b0.y); b2[1] = pack2(b0.z, b0.w);
            b2[2] = pack2(b1.x, b1.y); b2[3] = pack2(b1.z, b1.w);
            const float av[8] = {a0.x, a0.y, a0.z, a0.w, a1.x, a1.y, a1.z, a1.w};
#pragma unroll
            for (int i = 0; i < 8; i++) {
                const ull a2 = pack2(av[i], av[i]);
#pragma unroll
                for (int j = 0; j < 4; j++) acc[i][j] = ffma2(a2, b2[j], acc[i][j]);
            }
        }

        if (k1 < K) store_tile(cur ^ 1);     // opposite buffer; ordered by next sync
        cur ^= 1;
    }

    float lmax = -FLT_MAX;

#pragma unroll
    for (int i = 0; i < 8; i++) {
        float o[8];
#pragma unroll
        for (int j = 0; j < 4; j++) unpack2(acc[i][j], o[2 * j], o[2 * j + 1]);
        const long roff = (long)(m0 + tr * 8 + i) * ldc + n0;
        if (ADDX) {
            const float4 x0 = *(const float4*)(X + roff + tc * 4);
            const float4 x1 = *(const float4*)(X + roff + 64 + tc * 4);
            o[0] += x0.x; o[1] += x0.y; o[2] += x0.z; o[3] += x0.w;
            o[4] += x1.x; o[5] += x1.y; o[6] += x1.z; o[7] += x1.w;
        }
        if (STATS) {
#pragma unroll
            for (int j = 0; j < 8; j++) lmax = fmaxf(lmax, o[j]);
        }
        *(float4*)(C + roff + tc * 4)      = make_float4(o[0], o[1], o[2], o[3]);
        *(float4*)(C + roff + 64 + tc * 4) = make_float4(o[4], o[5], o[6], o[7]);
    }

    if (STATS) {
        // second pass over the (still-live) accumulators: sum exp(v - lmax)
        float lsum = 0.f;
#pragma unroll
        for (int i = 0; i < 8; i++)
#pragma unroll
            for (int j = 0; j < 4; j++) {
                float v0, v1; unpack2(acc[i][j], v0, v1);
                lsum += __expf(v0 - lmax) + __expf(v1 - lmax);
            }
        // warp-level online-softmax merge
#pragma unroll
        for (int s = 16; s; s >>= 1) {
            const float om = __shfl_xor_sync(0xffffffffu, lmax, s);
            const float os = __shfl_xor_sync(0xffffffffu, lsum, s);
            const float nm = fmaxf(lmax, om);
            lsum = lsum * __expf(lmax - nm) + os * __expf(om - nm);
            lmax = nm;
        }
        __shared__ float smx[8], sms[8];
        if ((tid & 31) == 0) { smx[tid >> 5] = lmax; sms[tid >> 5] = lsum; }
        __syncthreads();
        if (tid == 0) {
            float M = smx[0], S = sms[0];
#pragma unroll
            for (int w = 1; w < 8; w++) {
                const float nm = fmaxf(M, smx[w]);
                S = S * __expf(M - nm) + sms[w] * __expf(smx[w] - nm);
                M = nm;
            }
            const int tile = bz * 64 + blockIdx.y * 8 + blockIdx.x;
            g_tmax[tile] = M;
            g_tsum[tile] = S;
        }
    }
}

// ---------------------------------------------------------------------------
// One launch for both 256x256x256 weight products (perf-irrelevant, 8 blocks):
//   z=0: Mk   = Wt^T @ Wp   (A K-major)
//   z=1: Weff = Wr  @ Wg    (A row-major)
// ---------------------------------------------------------------------------
__global__ __launch_bounds__(256, 2) void weights_k(
    const float* __restrict__ wt, const float* __restrict__ wp,
    const float* __restrict__ wg, const float* __restrict__ wr)
{
    const bool ATm = (blockIdx.z == 0);
    const float* A = ATm ? wt : wr;
    const float* B = ATm ? wp : wg;
    float* C = g_wcat + blockIdx.z * CC * CC;

    const int m0 = blockIdx.y * 128;
    const int n0 = blockIdx.x * 128;
    const int tid = threadIdx.x;
    const int tr = tid >> 4;
    const int tc = tid & 15;

    __shared__ float As[16][132];
    __shared__ float Bs[16][128];

    ull acc[8][4];
#pragma unroll
    for (int i = 0; i < 8; i++)
#pragma unroll
        for (int j = 0; j < 4; j++) acc[i][j] = 0ull;

    for (int k0 = 0; k0 < CC; k0 += 16) {
        if (ATm) {
            // A[k][m], coalesced along m
            for (int i = tid; i < 512; i += 256) {
                const int k = i >> 5, mq = (i & 31) * 4;
                *(float4*)&As[k][mq] = *(const float4*)(A + (long)(k0 + k) * CC + m0 + mq);
            }
        } else {
            // A[m][k], float4 along k, transposed scatter
            for (int i = tid; i < 512; i += 256) {
                const int m = i >> 2, kq = (i & 3) * 4;
                const float4 v = *(const float4*)(A + (long)(m0 + m) * CC + k0 + kq);
                As[kq + 0][m] = v.x; As[kq + 1][m] = v.y;
                As[kq + 2][m] = v.z; As[kq + 3][m] = v.w;
            }
        }
        for (int i = tid; i < 512; i += 256) {
            const int k = i >> 5, nq = (i & 31) * 4;
            *(float4*)&Bs[k][nq] = *(const float4*)(B + (long)(k0 + k) * CC + n0 + nq);
        }
        __syncthreads();

#pragma unroll
        for (int k = 0; k < 16; k++) {
            const float4 b0 = *(const float4*)&Bs[k][tc * 4];
            const float4 b1 = *(const float4*)&Bs[k][64 + tc * 4];
            const float4 a0 = *(const float4*)&As[k][tr * 8];
            const float4 a1 = *(const float4*)&As[k][tr * 8 + 4];
            ull b2[4];
            b2[0] = pack2(b0.x, b0.y); b2[1] = pack2(b0.z, b0.w);
            b2[2] = pack2(b1.x, b1.y); b2[3] = pack2(b1.z, b1.w);
            const float av[8] = {a0.x, a0.y, a0.z, a0.w, a1.x, a1.y, a1.z, a1.w};
#pragma unroll
            for (int i = 0; i < 8; i++) {
                const ull a2 = pack2(av[i], av[i]);
#pragma unroll
                for (int j = 0; j < 4; j++) acc[i][j] = ffma2(a2, b2[j], acc[i][j]);
            }
        }
        __syncthreads();
    }

#pragma unroll
    for (int i = 0; i < 8; i++) {
        float o[8];
#pragma unroll
        for (int j = 0; j < 4; j++) unpack2(acc[i][j], o[2 * j], o[2 * j + 1]);
        const long roff = (long)(m0 + tr * 8 + i) * CC + n0;
        *(float4*)(C + roff + tc * 4)      = make_float4(o[0], o[1], o[2], o[3]);
        *(float4*)(C + roff + 64 + tc * 4) = make_float4(o[4], o[5], o[6], o[7]);
    }
}

// ---------------------------------------------------------------------------
extern "C" void kernel_launch(void* const* d_in, const int* in_sizes, int n_in,
                              void* d_out, int out_size)
{
    const float* x  = (const float*)d_in[0];
    const float* wt = (const float*)d_in[1];
    const float* wp = (const float*)d_in[2];
    const float* wg = (const float*)d_in[3];
    const float* wr = (const float*)d_in[4];

    float* outc = (float*)d_out;                       // c: [16, 1024, 1024]
    float* out2 = outc + (long)NB * LLEN * LLEN;       // x + attn: [16, 256, 32, 32]

    float *wcat, *qg;
    cudaGetSymbolAddress((void**)&wcat, g_wcat);
    cudaGetSymbolAddress((void**)&qg,   g_qg);

    const long sX  = (long)CC * LLEN;         // 262144: per-n stride of x / out2
    const long sQG = (long)2 * CC * LLEN;     // 524288
    const long sCC = (long)LLEN * LLEN;       // 1048576: per-n stride of c

    // Mk = Wt^T @ Wp, Weff = Wr @ Wg  (single launch, 8 blocks)
    weights_k<<<dim3(2, 2, 2), 256>>>(wt, wp, wg, wr);

    // q, geff = Wcat @ x[n]        [512 x 1024 x 256]
    gemm128<false, false, false, false><<<dim3(8, 4, NB), 256>>>(
        wcat, x, qg, nullptr, 256, 256, 1024, 1024, 0, sX, sQG);

    // c = x^T @ q  (+ per-tile softmax stats from registers)  -> d_out
    gemm128<true, false, false, true><<<dim3(8, 8, NB), 256>>>(
        x, qg, outc, nullptr, 256, 1024, 1024, 1024, sX, sQG, sCC);

    // out = x + geff @ softmax(c)  [256 x 1024 x 1024]:
    // tile stats folded in-kernel, exp(b - mxz) fused into B load,
    // residual fused into epilogue
    gemm128<false, true, true, false><<<dim3(8, 2, NB), 256>>>(
        qg + CC * LLEN, outc, out2, x, 1024, 1024, 1024, 1024, sQG, sCC, sX);
}